// round 14
// baseline (speedup 1.0000x reference)
#include <cuda_runtime.h>
#include <cuda_fp16.h>
#include <cstdint>

#define H 8
#define B 4
#define S 2048
#define D 8
#define F 64
#define HB 32
#define TILES 64
#define ROWS_CTA 32      // S / TILES
#define RPW 8            // rows per warp (4 warps)

typedef unsigned long long u64;

// Scratch (static __device__, no allocation). q fp32, k/v fp16; [hb][d][s].
__device__ float  g_q   [HB * D * S];       // pre-scaled by log2e/sqrt(8)
__device__ __half g_kTh [HB * D * S];
__device__ __half g_vTh [HB * D * S];
__device__ float  g_hpart[HB * D * TILES];  // [hb*8+d][tile] head-sum partials

__device__ __forceinline__ float ex2f(float x) {
    float y; asm("ex2.approx.ftz.f32 %0, %1;" : "=f"(y) : "f"(x)); return y;
}
__device__ __forceinline__ float rcpf(float x) {
    float y; asm("rcp.approx.ftz.f32 %0, %1;" : "=f"(y) : "f"(x)); return y;
}
__device__ __forceinline__ u64 fma2(u64 a, u64 b, u64 c) {
    u64 d; asm("fma.rn.f32x2 %0, %1, %2, %3;" : "=l"(d) : "l"(a), "l"(b), "l"(c)); return d;
}
__device__ __forceinline__ u64 mul2u(u64 a, u64 b) {
    u64 d; asm("mul.rn.f32x2 %0, %1, %2;" : "=l"(d) : "l"(a), "l"(b)); return d;
}
__device__ __forceinline__ u64 add2u(u64 a, u64 b) {
    u64 d; asm("add.rn.f32x2 %0, %1, %2;" : "=l"(d) : "l"(a), "l"(b)); return d;
}
__device__ __forceinline__ u64 pack2(float lo, float hi) {
    u64 d; asm("mov.b64 %0, {%1, %2};" : "=l"(d) : "f"(lo), "f"(hi)); return d;
}
__device__ __forceinline__ float2 unpk2(u64 a) {
    float2 r; asm("mov.b64 {%0, %1}, %2;" : "=f"(r.x), "=f"(r.y) : "l"(a)); return r;
}

// ---------------------------------------------------------------------------
// Kernel 1: QKV projection. grid 1024 x 192 thr, 8 rows/block — short
// per-thread critical path (128 LDS + 256 fma2) + more CTAs in flight.
// k AND v written fp16; q pre-scaled by log2e/sqrt(8). All [hb][d][s].
// ---------------------------------------------------------------------------
#define K1_ROWS 8
__global__ void __launch_bounds__(192) qkv_kernel(
    const float* __restrict__ x,
    const float* __restrict__ Wq,
    const float* __restrict__ Wk,
    const float* __restrict__ Wv)
{
    __shared__ float xs[K1_ROWS * 64];
    const int tid = threadIdx.x;
    const int rowbase = blockIdx.x * K1_ROWS;

    for (int i = tid; i < K1_ROWS * 64; i += 192)
        xs[i] = x[(size_t)rowbase * 64 + i];

    const int tensor = tid / 64;
    const int c = tid % 64;
    const int h = c >> 3, d = c & 7;
    const float* W = (tensor == 0) ? Wq : ((tensor == 1) ? Wk : Wv);

    // w packed over feature pairs
    u64 w2[32];
#pragma unroll
    for (int f2 = 0; f2 < 32; ++f2) {
        float wa = __ldg(&W[((size_t)h * 64 + 2 * f2 + 0) * 8 + d]);
        float wb = __ldg(&W[((size_t)h * 64 + 2 * f2 + 1) * 8 + d]);
        w2[f2] = pack2(wa, wb);
    }

    __syncthreads();

    u64 acc2[K1_ROWS];
#pragma unroll
    for (int r = 0; r < K1_ROWS; ++r) acc2[r] = 0ull;

#pragma unroll
    for (int f4 = 0; f4 < 16; ++f4) {
#pragma unroll
        for (int r = 0; r < K1_ROWS; ++r) {
            float4 xv = *(const float4*)&xs[r * 64 + f4 * 4];   // broadcast
            acc2[r] = fma2(pack2(xv.x, xv.y), w2[2 * f4 + 0], acc2[r]);
            acc2[r] = fma2(pack2(xv.z, xv.w), w2[2 * f4 + 1], acc2[r]);
        }
    }

    float acc[K1_ROWS];
#pragma unroll
    for (int r = 0; r < K1_ROWS; ++r) {
        float2 t = unpk2(acc2[r]);
        acc[r] = t.x + t.y;
    }

    const int b  = rowbase >> 11;
    const int s0 = rowbase & 2047;
    const int hb = h * 4 + b;
    const float QS = 0.51006975f;  // log2(e)/sqrt(8)
    if (tensor == 0) {
        float* dst = g_q + ((size_t)hb * 8 + d) * S + s0;
        *(float4*)(dst)     = make_float4(acc[0]*QS, acc[1]*QS, acc[2]*QS, acc[3]*QS);
        *(float4*)(dst + 4) = make_float4(acc[4]*QS, acc[5]*QS, acc[6]*QS, acc[7]*QS);
    } else {
        __half* dst = (tensor == 1 ? g_kTh : g_vTh) + ((size_t)hb * 8 + d) * S + s0;
        __half2 h01 = __floats2half2_rn(acc[0], acc[1]);
        __half2 h23 = __floats2half2_rn(acc[2], acc[3]);
        __half2 h45 = __floats2half2_rn(acc[4], acc[5]);
        __half2 h67 = __floats2half2_rn(acc[6], acc[7]);
        uint4 st;
        st.x = *(unsigned*)&h01; st.y = *(unsigned*)&h23;
        st.z = *(unsigned*)&h45; st.w = *(unsigned*)&h67;
        *(uint4*)dst = st;
    }
}

// ---------------------------------------------------------------------------
// Kernel 2: attention weights + fused head-sum partials (round-13 structure,
// tail store transposed to [hb*8+d][tile]).
// grid (TILES=64, HB=32), 128 threads, occ 3, smem 50KB.
// ---------------------------------------------------------------------------
__global__ void __launch_bounds__(128, 3) attn_kernel(float* __restrict__ wout)
{
    extern __shared__ float sm[];
    __half* kSh  = (__half*)sm;             // 16384 halfs (32KB) [d][s]; later v
    u64*    q2S  = (u64*)(sm + 8192);       // 256 u64 (2KB) {q,q}; later reduce buf
    __half* cshS = (__half*)(sm + 8704);    // 4 warps x 2048 halfs (16KB)

    const int tid  = threadIdx.x;
    const int lane = tid & 31;
    const int wrp  = tid >> 5;
    const int tile = blockIdx.x;
    const int hb   = blockIdx.y;

    {
        const uint4* k4 = (const uint4*)(g_kTh + (size_t)hb * D * S);
        uint4* kd = (uint4*)kSh;
#pragma unroll
        for (int i = 0; i < 16; ++i) kd[tid + 128 * i] = k4[tid + 128 * i];
#pragma unroll
        for (int i = tid; i < 256; i += 128) {
            const int r = i >> 3, d = i & 7;
            float q = g_q[((size_t)hb * 8 + d) * S + tile * ROWS_CTA + r];
            q2S[i] = pack2(q, q);
        }
    }
    __syncthreads();

    const int r0 = wrp * RPW;

    __half2 csh[32];
#pragma unroll
    for (int i = 0; i < 32; ++i) csh[i] = __half2half2(__ushort_as_half(0));

#pragma unroll 1
    for (int g = 0; g < 2; ++g) {
        const int rl = r0 + g * 4;

        u64 q2[4][8];
#pragma unroll
        for (int r = 0; r < 4; ++r)
#pragma unroll
            for (int j = 0; j < 4; ++j) {
                ulonglong2 t = *(const ulonglong2*)(q2S + (rl + r) * 8 + j * 2);
                q2[r][2*j] = t.x; q2[r][2*j+1] = t.y;
            }

        // ---- (a) denominator sweep for these 4 rows ----
        float ls[4] = {0.f, 0.f, 0.f, 0.f};
#pragma unroll 1
        for (int c = 0; c < 16; ++c) {
            const int col = c * 128 + lane * 4;
            u64 ka[8], kb[8];
#pragma unroll
            for (int d = 0; d < 8; ++d) {
                uint2 raw = *(const uint2*)(kSh + d * S + col);     // LDS.64
                float2 f01 = __half22float2(*(__half2*)&raw.x);
                float2 f23 = __half22float2(*(__half2*)&raw.y);
                ka[d] = pack2(f01.x, f01.y);
                kb[d] = pack2(f23.x, f23.y);
            }
#pragma unroll
            for (int r = 0; r < 4; ++r) {
                u64 sa = mul2u(q2[r][0], ka[0]);
                u64 sb = mul2u(q2[r][1], ka[1]);
                sa = fma2(q2[r][2], ka[2], sa); sb = fma2(q2[r][3], ka[3], sb);
                sa = fma2(q2[r][4], ka[4], sa); sb = fma2(q2[r][5], ka[5], sb);
                sa = fma2(q2[r][6], ka[6], sa); sb = fma2(q2[r][7], ka[7], sb);
                float2 s1 = unpk2(add2u(sa, sb));
                u64 ta = mul2u(q2[r][0], kb[0]);
                u64 tb = mul2u(q2[r][1], kb[1]);
                ta = fma2(q2[r][2], kb[2], ta); tb = fma2(q2[r][3], kb[3], tb);
                ta = fma2(q2[r][4], kb[4], ta); tb = fma2(q2[r][5], kb[5], tb);
                ta = fma2(q2[r][6], kb[6], ta); tb = fma2(q2[r][7], kb[7], tb);
                float2 s2 = unpk2(add2u(ta, tb));
                ls[r] += (ex2f(s1.x) + ex2f(s1.y)) + (ex2f(s2.x) + ex2f(s2.y));
            }
        }

        u64 iv2[4];
#pragma unroll
        for (int r = 0; r < 4; ++r) {
            float v = ls[r];
#pragma unroll
            for (int o = 16; o > 0; o >>= 1) v += __shfl_xor_sync(0xffffffffu, v, o);
            float iv = rcpf(v);
            iv2[r] = pack2(iv, iv);
        }

        // ---- (b) recompute + normalize + store sweep (same 4 rows) ----
        const size_t wb = ((size_t)hb * S + (size_t)tile * ROWS_CTA + rl) * S;
#pragma unroll 1
        for (int c = 0; c < 16; ++c) {
            const int col = c * 128 + lane * 4;
            u64 ka[8], kb[8];
#pragma unroll
            for (int d = 0; d < 8; ++d) {
                uint2 raw = *(const uint2*)(kSh + d * S + col);
                float2 f01 = __half22float2(*(__half2*)&raw.x);
                float2 f23 = __half22float2(*(__half2*)&raw.y);
                ka[d] = pack2(f01.x, f01.y);
                kb[d] = pack2(f23.x, f23.y);
            }
#pragma unroll
            for (int r = 0; r < 4; ++r) {
                u64 sa = mul2u(q2[r][0], ka[0]);
                u64 sb = mul2u(q2[r][1], ka[1]);
                sa = fma2(q2[r][2], ka[2], sa); sb = fma2(q2[r][3], ka[3], sb);
                sa = fma2(q2[r][4], ka[4], sa); sb = fma2(q2[r][5], ka[5], sb);
                sa = fma2(q2[r][6], ka[6], sa); sb = fma2(q2[r][7], ka[7], sb);
                float2 s1 = unpk2(add2u(sa, sb));
                u64 ta = mul2u(q2[r][0], kb[0]);
                u64 tb = mul2u(q2[r][1], kb[1]);
                ta = fma2(q2[r][2], kb[2], ta); tb = fma2(q2[r][3], kb[3], tb);
                ta = fma2(q2[r][4], kb[4], ta); tb = fma2(q2[r][5], kb[5], tb);
                ta = fma2(q2[r][6], kb[6], ta); tb = fma2(q2[r][7], kb[7], tb);
                float2 s2 = unpk2(add2u(ta, tb));

                u64 w0 = mul2u(pack2(ex2f(s1.x), ex2f(s1.y)), iv2[r]);
                u64 w1 = mul2u(pack2(ex2f(s2.x), ex2f(s2.y)), iv2[r]);
                float2 a = unpk2(w0);
                float2 b = unpk2(w1);
                csh[2*c+0] = __hadd2(csh[2*c+0], __floats2half2_rn(a.x, a.y));
                csh[2*c+1] = __hadd2(csh[2*c+1], __floats2half2_rn(b.x, b.y));
                __stcs((float4*)(wout + wb + (size_t)r * S + col),
                       make_float4(a.x, a.y, b.x, b.y));
            }
        }
    }

    // ---------------- fused head-sum: colsums -> smem, v -> dead k region ---
    __syncthreads();     // main loop done everywhere (k reads finished)
    {
        __half* csW = cshS + wrp * S;
#pragma unroll
        for (int c = 0; c < 16; ++c) {
            const int col = c * 128 + lane * 4;
            uint2 st;
            st.x = *(unsigned*)&csh[2*c+0];
            st.y = *(unsigned*)&csh[2*c+1];
            *(uint2*)(csW + col) = st;
        }
        // v fp16 tile into kSh (k no longer needed)
        const uint4* v4 = (const uint4*)(g_vTh + (size_t)hb * D * S);
        uint4* vd = (uint4*)kSh;
#pragma unroll
        for (int i = 0; i < 16; ++i) vd[tid + 128 * i] = v4[tid + 128 * i];
    }
    __syncthreads();
    {
        const int j0 = tid * 16;
        float csv[16];
#pragma unroll
        for (int jj = 0; jj < 16; ++jj) {
            float s = 0.f;
#pragma unroll
            for (int w = 0; w < 4; ++w)
                s += __half2float(cshS[w * S + j0 + jj]);
            csv[jj] = s;
        }
        float p[8];
#pragma unroll
        for (int d = 0; d < 8; ++d) {
            float s = 0.f;
#pragma unroll
            for (int jj = 0; jj < 16; ++jj)
                s += csv[jj] * __half2float(kSh[d * S + j0 + jj]);
            p[d] = s;
        }
        // block reduce: warp shuffles, then 4 partials via q2S (reused)
        float* redS = (float*)q2S;
#pragma unroll
        for (int d = 0; d < 8; ++d) {
            float v = p[d];
#pragma unroll
            for (int o = 16; o > 0; o >>= 1) v += __shfl_xor_sync(0xffffffffu, v, o);
            p[d] = v;
        }
        if (lane == 0) {
#pragma unroll
            for (int d = 0; d < 8; ++d) redS[wrp * 8 + d] = p[d];
        }
        __syncthreads();
        if (tid < 8) {
            float s = redS[tid] + redS[8 + tid] + redS[16 + tid] + redS[24 + tid];
            g_hpart[((size_t)hb * 8 + tid) * TILES + tile] = s;   // transposed
        }
    }
}

// ---------------------------------------------------------------------------
// Kernel 3: out[b][f] = sum_{h,d} (sum_tile hpart[hb*8+d][tile]) * Wo[h*8+d][f]
// hpart rows contiguous -> each thread does 16 float4 loads (MLP 16).
// ---------------------------------------------------------------------------
__global__ void __launch_bounds__(256) out_kernel(
    const float* __restrict__ Wo, float* __restrict__ out)
{
    __shared__ float hs[256];
    const int t = threadIdx.x;
    {
        const int b = t >> 6, j = t & 63;
        const int h = j >> 3, d = j & 7;
        const int hb = h * 4 + b;
        const float* src = g_hpart + ((size_t)hb * 8 + d) * TILES;
        float s = 0.f;
#pragma unroll
        for (int i = 0; i < 16; ++i) {
            float4 a = *(const float4*)(src + 4 * i);
            s += (a.x + a.y) + (a.z + a.w);
        }
        hs[t] = s;
    }
    __syncthreads();
    const int b = t >> 6, f = t & 63;
    float a = 0.f;
#pragma unroll
    for (int j = 0; j < 64; ++j)
        a = fmaf(hs[b * 64 + j], Wo[j * 64 + f], a);
    out[b * 64 + f] = a;
}

// ---------------------------------------------------------------------------
extern "C" void kernel_launch(void* const* d_in, const int* in_sizes, int n_in,
                              void* d_out, int out_size)
{
    const float* x  = (const float*)d_in[0];
    const float* Wq = (const float*)d_in[1];
    const float* Wk = (const float*)d_in[2];
    const float* Wv = (const float*)d_in[3];
    const float* Wo = (const float*)d_in[4];
    float* out = (float*)d_out;

    const long long WELEMS = (long long)HB * S * S;  // 134217728
    float* wout = out;
    bool has_sum = false;
    if ((long long)out_size >= WELEMS + 256) {  // [sum(256) | weights]
        wout = out + 256;
        has_sum = true;
    }

    const int k2_smem = (8192 + 512 + 4096) * 4;  // 51200
    cudaFuncSetAttribute(attn_kernel, cudaFuncAttributeMaxDynamicSharedMemorySize, k2_smem);

    qkv_kernel<<<(B * S) / K1_ROWS, 192>>>(x, Wq, Wk, Wv);
    attn_kernel<<<dim3(TILES, HB), 128, k2_smem>>>(wout);
    if (has_sum) out_kernel<<<1, 256>>>(Wo, out);
}

// round 15
// speedup vs baseline: 1.0381x; 1.0381x over previous
#include <cuda_runtime.h>
#include <cuda_fp16.h>
#include <cstdint>

#define H 8
#define B 4
#define S 2048
#define D 8
#define F 64
#define HB 32
#define TILES 32
#define ROWS_CTA 64      // S / TILES
#define RPW 16           // rows per warp (4 warps)

typedef unsigned long long u64;

// Scratch (static __device__, no allocation). q fp32, k/v fp16; [hb][d][s].
__device__ float  g_q   [HB * D * S];       // pre-scaled by log2e/sqrt(8)
__device__ __half g_kTh [HB * D * S];
__device__ __half g_vTh [HB * D * S];
__device__ float  g_hpart[HB * D * TILES];  // [hb*8+d][tile] head-sum partials

__device__ __forceinline__ float ex2f(float x) {
    float y; asm("ex2.approx.ftz.f32 %0, %1;" : "=f"(y) : "f"(x)); return y;
}
__device__ __forceinline__ float rcpf(float x) {
    float y; asm("rcp.approx.ftz.f32 %0, %1;" : "=f"(y) : "f"(x)); return y;
}
__device__ __forceinline__ u64 fma2(u64 a, u64 b, u64 c) {
    u64 d; asm("fma.rn.f32x2 %0, %1, %2, %3;" : "=l"(d) : "l"(a), "l"(b), "l"(c)); return d;
}
__device__ __forceinline__ u64 mul2u(u64 a, u64 b) {
    u64 d; asm("mul.rn.f32x2 %0, %1, %2;" : "=l"(d) : "l"(a), "l"(b)); return d;
}
__device__ __forceinline__ u64 add2u(u64 a, u64 b) {
    u64 d; asm("add.rn.f32x2 %0, %1, %2;" : "=l"(d) : "l"(a), "l"(b)); return d;
}
__device__ __forceinline__ u64 pack2(float lo, float hi) {
    u64 d; asm("mov.b64 %0, {%1, %2};" : "=l"(d) : "f"(lo), "f"(hi)); return d;
}
__device__ __forceinline__ float2 unpk2(u64 a) {
    float2 r; asm("mov.b64 {%0, %1}, %2;" : "=f"(r.x), "=f"(r.y) : "l"(a)); return r;
}

// ---------------------------------------------------------------------------
// Kernel 1: QKV projection. grid 512 x 192 thr, 16 rows/block.
// W staged through smem (coalesced float4, conflict-free padded reads) then
// copied to per-thread registers — no long-scoreboard LDGs in the dot loop.
// k AND v written fp16; q pre-scaled by log2e/sqrt(8). All [hb][d][s].
// ---------------------------------------------------------------------------
#define K1_ROWS 16
#define WPAD 520     // 512 + 8 pad floats per head -> all 32 banks covered
__global__ void __launch_bounds__(192) qkv_kernel(
    const float* __restrict__ x,
    const float* __restrict__ Wq,
    const float* __restrict__ Wk,
    const float* __restrict__ Wv)
{
    extern __shared__ float k1sm[];
    float* xs = k1sm;                  // 1024 floats
    float* Ws = k1sm + 1024;           // 3 * 8 * 520 = 12480 floats

    const int tid = threadIdx.x;
    const int rowbase = blockIdx.x * K1_ROWS;

    for (int i = tid; i < K1_ROWS * 64; i += 192)
        xs[i] = x[(size_t)rowbase * 64 + i];
    {
        const float* Wsrc[3] = {Wq, Wk, Wv};
#pragma unroll
        for (int t3 = 0; t3 < 3; ++t3) {
            const float4* W4 = (const float4*)Wsrc[t3];
            for (int i = tid; i < 1024; i += 192) {       // 4096 floats as float4
                float4 v = W4[i];
                const int base = i * 4;
                const int hh = base >> 9, rem = base & 511;
                float* dst = Ws + t3 * (8 * WPAD) + hh * WPAD + rem;
                dst[0] = v.x; dst[1] = v.y; dst[2] = v.z; dst[3] = v.w;
            }
        }
    }
    __syncthreads();

    const int tensor = tid / 64;
    const int c = tid % 64;
    const int h = c >> 3, d = c & 7;
    const float* Wc = Ws + tensor * (8 * WPAD) + h * WPAD;

    // copy my column to registers, packed over feature pairs (LDS, lat 29)
    u64 w2[32];
#pragma unroll
    for (int f2 = 0; f2 < 32; ++f2) {
        float wa = Wc[(2 * f2 + 0) * 8 + d];
        float wb = Wc[(2 * f2 + 1) * 8 + d];
        w2[f2] = pack2(wa, wb);
    }

    u64 acc2[K1_ROWS];
#pragma unroll
    for (int r = 0; r < K1_ROWS; ++r) acc2[r] = 0ull;

#pragma unroll
    for (int f4 = 0; f4 < 16; ++f4) {
#pragma unroll
        for (int r = 0; r < K1_ROWS; ++r) {
            float4 xv = *(const float4*)&xs[r * 64 + f4 * 4];   // broadcast
            acc2[r] = fma2(pack2(xv.x, xv.y), w2[2 * f4 + 0], acc2[r]);
            acc2[r] = fma2(pack2(xv.z, xv.w), w2[2 * f4 + 1], acc2[r]);
        }
    }

    float acc[K1_ROWS];
#pragma unroll
    for (int r = 0; r < K1_ROWS; ++r) {
        float2 t = unpk2(acc2[r]);
        acc[r] = t.x + t.y;
    }

    const int b  = rowbase >> 11;
    const int s0 = rowbase & 2047;
    const int hb = h * 4 + b;
    const float QS = 0.51006975f;  // log2(e)/sqrt(8)
    if (tensor == 0) {
        float* dst = g_q + ((size_t)hb * 8 + d) * S + s0;
#pragma unroll
        for (int i = 0; i < K1_ROWS / 4; ++i)
            *(float4*)(dst + 4 * i) = make_float4(acc[4*i]*QS, acc[4*i+1]*QS,
                                                  acc[4*i+2]*QS, acc[4*i+3]*QS);
    } else {
        __half* dst = (tensor == 1 ? g_kTh : g_vTh) + ((size_t)hb * 8 + d) * S + s0;
#pragma unroll
        for (int i = 0; i < K1_ROWS / 8; ++i) {
            __half2 h01 = __floats2half2_rn(acc[8*i+0], acc[8*i+1]);
            __half2 h23 = __floats2half2_rn(acc[8*i+2], acc[8*i+3]);
            __half2 h45 = __floats2half2_rn(acc[8*i+4], acc[8*i+5]);
            __half2 h67 = __floats2half2_rn(acc[8*i+6], acc[8*i+7]);
            uint4 st;
            st.x = *(unsigned*)&h01; st.y = *(unsigned*)&h23;
            st.z = *(unsigned*)&h45; st.w = *(unsigned*)&h67;
            *(uint4*)(dst + 8 * i) = st;
        }
    }
}

// ---------------------------------------------------------------------------
// Kernel 2: attention weights + fused head-sum partials.
// grid (TILES=32, HB=32), 128 threads, occ 3, smem 53.2KB.
// Round-13 inner structure; per CTA 64 rows (RPW=16, 4 groups of 4 rows):
// per group (a) denominator sweep (k fp16 smem -> regs, exp2 sums, shfl
// reduce, inv in regs) then (b) recompute+normalize+__stcs store + half2
// colsums. Tail: colsums -> smem, v fp16 into dead k region, 16-col dots ->
// block reduce -> g_hpart[hb*8+d][tile].
// ---------------------------------------------------------------------------
__global__ void __launch_bounds__(128, 3) attn_kernel(float* __restrict__ wout)
{
    extern __shared__ float sm[];
    __half* kSh  = (__half*)sm;             // 16384 halfs (32KB) [d][s]; later v
    u64*    q2S  = (u64*)(sm + 8192);       // 64 rows x 8 d (4KB); later reduce buf
    __half* cshS = (__half*)(sm + 9216);    // 4 warps x 2048 halfs (16KB)

    const int tid  = threadIdx.x;
    const int lane = tid & 31;
    const int wrp  = tid >> 5;
    const int tile = blockIdx.x;
    const int hb   = blockIdx.y;

    {
        const uint4* k4 = (const uint4*)(g_kTh + (size_t)hb * D * S);
        uint4* kd = (uint4*)kSh;
#pragma unroll
        for (int i = 0; i < 16; ++i) kd[tid + 128 * i] = k4[tid + 128 * i];
#pragma unroll
        for (int i = tid; i < ROWS_CTA * 8; i += 128) {
            const int r = i >> 3, d = i & 7;
            float q = g_q[((size_t)hb * 8 + d) * S + tile * ROWS_CTA + r];
            q2S[i] = pack2(q, q);
        }
    }
    __syncthreads();

    const int r0 = wrp * RPW;

    __half2 csh[32];
#pragma unroll
    for (int i = 0; i < 32; ++i) csh[i] = __half2half2(__ushort_as_half(0));

#pragma unroll 1
    for (int g = 0; g < 4; ++g) {
        const int rl = r0 + g * 4;

        u64 q2[4][8];
#pragma unroll
        for (int r = 0; r < 4; ++r)
#pragma unroll
            for (int j = 0; j < 4; ++j) {
                ulonglong2 t = *(const ulonglong2*)(q2S + (rl + r) * 8 + j * 2);
                q2[r][2*j] = t.x; q2[r][2*j+1] = t.y;
            }

        // ---- (a) denominator sweep for these 4 rows ----
        float ls[4] = {0.f, 0.f, 0.f, 0.f};
#pragma unroll 1
        for (int c = 0; c < 16; ++c) {
            const int col = c * 128 + lane * 4;
            u64 ka[8], kb[8];
#pragma unroll
            for (int d = 0; d < 8; ++d) {
                uint2 raw = *(const uint2*)(kSh + d * S + col);     // LDS.64
                float2 f01 = __half22float2(*(__half2*)&raw.x);
                float2 f23 = __half22float2(*(__half2*)&raw.y);
                ka[d] = pack2(f01.x, f01.y);
                kb[d] = pack2(f23.x, f23.y);
            }
#pragma unroll
            for (int r = 0; r < 4; ++r) {
                u64 sa = mul2u(q2[r][0], ka[0]);
                u64 sb = mul2u(q2[r][1], ka[1]);
                sa = fma2(q2[r][2], ka[2], sa); sb = fma2(q2[r][3], ka[3], sb);
                sa = fma2(q2[r][4], ka[4], sa); sb = fma2(q2[r][5], ka[5], sb);
                sa = fma2(q2[r][6], ka[6], sa); sb = fma2(q2[r][7], ka[7], sb);
                float2 s1 = unpk2(add2u(sa, sb));
                u64 ta = mul2u(q2[r][0], kb[0]);
                u64 tb = mul2u(q2[r][1], kb[1]);
                ta = fma2(q2[r][2], kb[2], ta); tb = fma2(q2[r][3], kb[3], tb);
                ta = fma2(q2[r][4], kb[4], ta); tb = fma2(q2[r][5], kb[5], tb);
                ta = fma2(q2[r][6], kb[6], ta); tb = fma2(q2[r][7], kb[7], tb);
                float2 s2 = unpk2(add2u(ta, tb));
                ls[r] += (ex2f(s1.x) + ex2f(s1.y)) + (ex2f(s2.x) + ex2f(s2.y));
            }
        }

        u64 iv2[4];
#pragma unroll
        for (int r = 0; r < 4; ++r) {
            float v = ls[r];
#pragma unroll
            for (int o = 16; o > 0; o >>= 1) v += __shfl_xor_sync(0xffffffffu, v, o);
            float iv = rcpf(v);
            iv2[r] = pack2(iv, iv);
        }

        // ---- (b) recompute + normalize + store sweep (same 4 rows) ----
        const size_t wb = ((size_t)hb * S + (size_t)tile * ROWS_CTA + rl) * S;
#pragma unroll 1
        for (int c = 0; c < 16; ++c) {
            const int col = c * 128 + lane * 4;
            u64 ka[8], kb[8];
#pragma unroll
            for (int d = 0; d < 8; ++d) {
                uint2 raw = *(const uint2*)(kSh + d * S + col);
                float2 f01 = __half22float2(*(__half2*)&raw.x);
                float2 f23 = __half22float2(*(__half2*)&raw.y);
                ka[d] = pack2(f01.x, f01.y);
                kb[d] = pack2(f23.x, f23.y);
            }
#pragma unroll
            for (int r = 0; r < 4; ++r) {
                u64 sa = mul2u(q2[r][0], ka[0]);
                u64 sb = mul2u(q2[r][1], ka[1]);
                sa = fma2(q2[r][2], ka[2], sa); sb = fma2(q2[r][3], ka[3], sb);
                sa = fma2(q2[r][4], ka[4], sa); sb = fma2(q2[r][5], ka[5], sb);
                sa = fma2(q2[r][6], ka[6], sa); sb = fma2(q2[r][7], ka[7], sb);
                float2 s1 = unpk2(add2u(sa, sb));
                u64 ta = mul2u(q2[r][0], kb[0]);
                u64 tb = mul2u(q2[r][1], kb[1]);
                ta = fma2(q2[r][2], kb[2], ta); tb = fma2(q2[r][3], kb[3], tb);
                ta = fma2(q2[r][4], kb[4], ta); tb = fma2(q2[r][5], kb[5], tb);
                ta = fma2(q2[r][6], kb[6], ta); tb = fma2(q2[r][7], kb[7], tb);
                float2 s2 = unpk2(add2u(ta, tb));

                u64 w0 = mul2u(pack2(ex2f(s1.x), ex2f(s1.y)), iv2[r]);
                u64 w1 = mul2u(pack2(ex2f(s2.x), ex2f(s2.y)), iv2[r]);
                float2 a = unpk2(w0);
                float2 b = unpk2(w1);
                csh[2*c+0] = __hadd2(csh[2*c+0], __floats2half2_rn(a.x, a.y));
                csh[2*c+1] = __hadd2(csh[2*c+1], __floats2half2_rn(b.x, b.y));
                __stcs((float4*)(wout + wb + (size_t)r * S + col),
                       make_float4(a.x, a.y, b.x, b.y));
            }
        }
    }

    // ---------------- fused head-sum: colsums -> smem, v -> dead k region ---
    __syncthreads();     // main loop done everywhere (k reads finished)
    {
        __half* csW = cshS + wrp * S;
#pragma unroll
        for (int c = 0; c < 16; ++c) {
            const int col = c * 128 + lane * 4;
            uint2 st;
            st.x = *(unsigned*)&csh[2*c+0];
            st.y = *(unsigned*)&csh[2*c+1];
            *(uint2*)(csW + col) = st;
        }
        // v fp16 tile into kSh (k no longer needed)
        const uint4* v4 = (const uint4*)(g_vTh + (size_t)hb * D * S);
        uint4* vd = (uint4*)kSh;
#pragma unroll
        for (int i = 0; i < 16; ++i) vd[tid + 128 * i] = v4[tid + 128 * i];
    }
    __syncthreads();
    {
        const int j0 = tid * 16;
        float csv[16];
#pragma unroll
        for (int jj = 0; jj < 16; ++jj) {
            float s = 0.f;
#pragma unroll
            for (int w = 0; w < 4; ++w)
                s += __half2float(cshS[w * S + j0 + jj]);
            csv[jj] = s;
        }
        float p[8];
#pragma unroll
        for (int d = 0; d < 8; ++d) {
            float s = 0.f;
#pragma unroll
            for (int jj = 0; jj < 16; ++jj)
                s += csv[jj] * __half2float(kSh[d * S + j0 + jj]);
            p[d] = s;
        }
        float* redS = (float*)q2S;
#pragma unroll
        for (int d = 0; d < 8; ++d) {
            float v = p[d];
#pragma unroll
            for (int o = 16; o > 0; o >>= 1) v += __shfl_xor_sync(0xffffffffu, v, o);
            p[d] = v;
        }
        if (lane == 0) {
#pragma unroll
            for (int d = 0; d < 8; ++d) redS[wrp * 8 + d] = p[d];
        }
        __syncthreads();
        if (tid < 8) {
            float s = redS[tid] + redS[8 + tid] + redS[16 + tid] + redS[24 + tid];
            g_hpart[((size_t)hb * 8 + tid) * TILES + tile] = s;   // transposed
        }
    }
}

// ---------------------------------------------------------------------------
// Kernel 3: out[b][f] = sum_{h,d} (sum_tile hpart[hb*8+d][tile]) * Wo[h*8+d][f]
// ---------------------------------------------------------------------------
__global__ void __launch_bounds__(256) out_kernel(
    const float* __restrict__ Wo, float* __restrict__ out)
{
    __shared__ float hs[256];
    const int t = threadIdx.x;
    {
        const int b = t >> 6, j = t & 63;
        const int h = j >> 3, d = j & 7;
        const int hb = h * 4 + b;
        const float* src = g_hpart + ((size_t)hb * 8 + d) * TILES;
        float s = 0.f;
#pragma unroll
        for (int i = 0; i < TILES / 4; ++i) {
            float4 a = *(const float4*)(src + 4 * i);
            s += (a.x + a.y) + (a.z + a.w);
        }
        hs[t] = s;
    }
    __syncthreads();
    const int b = t >> 6, f = t & 63;
    float a = 0.f;
#pragma unroll
    for (int j = 0; j < 64; ++j)
        a = fmaf(hs[b * 64 + j], Wo[j * 64 + f], a);
    out[b * 64 + f] = a;
}

// ---------------------------------------------------------------------------
extern "C" void kernel_launch(void* const* d_in, const int* in_sizes, int n_in,
                              void* d_out, int out_size)
{
    const float* x  = (const float*)d_in[0];
    const float* Wq = (const float*)d_in[1];
    const float* Wk = (const float*)d_in[2];
    const float* Wv = (const float*)d_in[3];
    const float* Wo = (const float*)d_in[4];
    float* out = (float*)d_out;

    const long long WELEMS = (long long)HB * S * S;  // 134217728
    float* wout = out;
    bool has_sum = false;
    if ((long long)out_size >= WELEMS + 256) {  // [sum(256) | weights]
        wout = out + 256;
        has_sum = true;
    }

    const int k1_smem = (1024 + 3 * 8 * WPAD) * 4;  // 54016
    const int k2_smem = (8192 + 1024 + 4096) * 4;   // 53248
    cudaFuncSetAttribute(qkv_kernel,  cudaFuncAttributeMaxDynamicSharedMemorySize, k1_smem);
    cudaFuncSetAttribute(attn_kernel, cudaFuncAttributeMaxDynamicSharedMemorySize, k2_smem);

    qkv_kernel<<<(B * S) / K1_ROWS, 192, k1_smem>>>(x, Wq, Wk, Wv);
    attn_kernel<<<dim3(TILES, HB), 128, k2_smem>>>(wout);
    if (has_sum) out_kernel<<<1, 256>>>(Wo, out);
}

// round 16
// speedup vs baseline: 1.0417x; 1.0034x over previous
#include <cuda_runtime.h>
#include <cuda_fp16.h>
#include <cstdint>

#define H 8
#define B 4
#define S 2048
#define D 8
#define F 64
#define HB 32
#define TILES 32
#define ROWS_CTA 64      // S / TILES
#define RPW 16           // rows per warp (4 warps)

typedef unsigned long long u64;

// Scratch (static __device__, no allocation). q fp32, k/v fp16; [hb][d][s].
__device__ float  g_q   [HB * D * S];       // pre-scaled by log2e/sqrt(8)
__device__ __half g_kTh [HB * D * S];
__device__ __half g_vTh [HB * D * S];
__device__ float  g_hpart[HB * D * TILES];  // [hb*8+d][tile] head-sum partials

__device__ __forceinline__ float ex2f(float x) {
    float y; asm("ex2.approx.ftz.f32 %0, %1;" : "=f"(y) : "f"(x)); return y;
}
__device__ __forceinline__ float rcpf(float x) {
    float y; asm("rcp.approx.ftz.f32 %0, %1;" : "=f"(y) : "f"(x)); return y;
}
__device__ __forceinline__ u64 fma2(u64 a, u64 b, u64 c) {
    u64 d; asm("fma.rn.f32x2 %0, %1, %2, %3;" : "=l"(d) : "l"(a), "l"(b), "l"(c)); return d;
}
__device__ __forceinline__ u64 mul2u(u64 a, u64 b) {
    u64 d; asm("mul.rn.f32x2 %0, %1, %2;" : "=l"(d) : "l"(a), "l"(b)); return d;
}
__device__ __forceinline__ u64 add2u(u64 a, u64 b) {
    u64 d; asm("add.rn.f32x2 %0, %1, %2;" : "=l"(d) : "l"(a), "l"(b)); return d;
}
__device__ __forceinline__ u64 pack2(float lo, float hi) {
    u64 d; asm("mov.b64 %0, {%1, %2};" : "=l"(d) : "f"(lo), "f"(hi)); return d;
}
__device__ __forceinline__ float2 unpk2(u64 a) {
    float2 r; asm("mov.b64 {%0, %1}, %2;" : "=f"(r.x), "=f"(r.y) : "l"(a)); return r;
}

// ---------------------------------------------------------------------------
// Kernel 1: QKV projection — ROUND-13 variant verbatim (best measured:
// 17.4us). grid 512 x 192 thr, 16 rows/block, per-thread W column via __ldg
// (L2-hot, 12KB total), x staged in smem, fma2-packed dot products.
// k AND v written fp16; q pre-scaled by log2e/sqrt(8). All [hb][d][s].
// ---------------------------------------------------------------------------
#define K1_ROWS 16
__global__ void __launch_bounds__(192) qkv_kernel(
    const float* __restrict__ x,
    const float* __restrict__ Wq,
    const float* __restrict__ Wk,
    const float* __restrict__ Wv)
{
    __shared__ float xs[K1_ROWS * 64];
    const int tid = threadIdx.x;
    const int rowbase = blockIdx.x * K1_ROWS;

    for (int i = tid; i < K1_ROWS * 64; i += 192)
        xs[i] = x[(size_t)rowbase * 64 + i];

    const int tensor = tid / 64;
    const int c = tid % 64;
    const int h = c >> 3, d = c & 7;
    const float* W = (tensor == 0) ? Wq : ((tensor == 1) ? Wk : Wv);

    // w packed over feature pairs: w2[f2] = {w[2f2], w[2f2+1]}
    u64 w2[32];
#pragma unroll
    for (int f2 = 0; f2 < 32; ++f2) {
        float wa = __ldg(&W[((size_t)h * 64 + 2 * f2 + 0) * 8 + d]);
        float wb = __ldg(&W[((size_t)h * 64 + 2 * f2 + 1) * 8 + d]);
        w2[f2] = pack2(wa, wb);
    }

    __syncthreads();

    u64 acc2[K1_ROWS];
#pragma unroll
    for (int r = 0; r < K1_ROWS; ++r) acc2[r] = 0ull;

#pragma unroll
    for (int f4 = 0; f4 < 16; ++f4) {
#pragma unroll
        for (int r = 0; r < K1_ROWS; ++r) {
            float4 xv = *(const float4*)&xs[r * 64 + f4 * 4];   // broadcast
            acc2[r] = fma2(pack2(xv.x, xv.y), w2[2 * f4 + 0], acc2[r]);
            acc2[r] = fma2(pack2(xv.z, xv.w), w2[2 * f4 + 1], acc2[r]);
        }
    }

    float acc[K1_ROWS];
#pragma unroll
    for (int r = 0; r < K1_ROWS; ++r) {
        float2 t = unpk2(acc2[r]);
        acc[r] = t.x + t.y;
    }

    const int b  = rowbase >> 11;
    const int s0 = rowbase & 2047;
    const int hb = h * 4 + b;
    const float QS = 0.51006975f;  // log2(e)/sqrt(8)
    if (tensor == 0) {
        float* dst = g_q + ((size_t)hb * 8 + d) * S + s0;
#pragma unroll
        for (int i = 0; i < K1_ROWS / 4; ++i)
            *(float4*)(dst + 4 * i) = make_float4(acc[4*i]*QS, acc[4*i+1]*QS,
                                                  acc[4*i+2]*QS, acc[4*i+3]*QS);
    } else {
        __half* dst = (tensor == 1 ? g_kTh : g_vTh) + ((size_t)hb * 8 + d) * S + s0;
#pragma unroll
        for (int i = 0; i < K1_ROWS / 8; ++i) {
            __half2 h01 = __floats2half2_rn(acc[8*i+0], acc[8*i+1]);
            __half2 h23 = __floats2half2_rn(acc[8*i+2], acc[8*i+3]);
            __half2 h45 = __floats2half2_rn(acc[8*i+4], acc[8*i+5]);
            __half2 h67 = __floats2half2_rn(acc[8*i+6], acc[8*i+7]);
            uint4 st;
            st.x = *(unsigned*)&h01; st.y = *(unsigned*)&h23;
            st.z = *(unsigned*)&h45; st.w = *(unsigned*)&h67;
            *(uint4*)(dst + 8 * i) = st;
        }
    }
}

// ---------------------------------------------------------------------------
// Kernel 2: attention weights + fused head-sum partials — ROUND-15 verbatim.
// grid (TILES=32, HB=32), 128 threads, occ 3, smem 53.2KB.
// Per CTA 64 rows (RPW=16, 4 groups of 4 rows): per group (a) denominator
// sweep then (b) recompute+normalize+__stcs store + half2 colsums.
// Tail: colsums -> smem, v fp16 into dead k region, 16-col dots ->
// block reduce -> g_hpart[hb*8+d][tile].
// ---------------------------------------------------------------------------
__global__ void __launch_bounds__(128, 3) attn_kernel(float* __restrict__ wout)
{
    extern __shared__ float sm[];
    __half* kSh  = (__half*)sm;             // 16384 halfs (32KB) [d][s]; later v
    u64*    q2S  = (u64*)(sm + 8192);       // 64 rows x 8 d (4KB); later reduce buf
    __half* cshS = (__half*)(sm + 9216);    // 4 warps x 2048 halfs (16KB)

    const int tid  = threadIdx.x;
    const int lane = tid & 31;
    const int wrp  = tid >> 5;
    const int tile = blockIdx.x;
    const int hb   = blockIdx.y;

    {
        const uint4* k4 = (const uint4*)(g_kTh + (size_t)hb * D * S);
        uint4* kd = (uint4*)kSh;
#pragma unroll
        for (int i = 0; i < 16; ++i) kd[tid + 128 * i] = k4[tid + 128 * i];
#pragma unroll
        for (int i = tid; i < ROWS_CTA * 8; i += 128) {
            const int r = i >> 3, d = i & 7;
            float q = g_q[((size_t)hb * 8 + d) * S + tile * ROWS_CTA + r];
            q2S[i] = pack2(q, q);
        }
    }
    __syncthreads();

    const int r0 = wrp * RPW;

    __half2 csh[32];
#pragma unroll
    for (int i = 0; i < 32; ++i) csh[i] = __half2half2(__ushort_as_half(0));

#pragma unroll 1
    for (int g = 0; g < 4; ++g) {
        const int rl = r0 + g * 4;

        u64 q2[4][8];
#pragma unroll
        for (int r = 0; r < 4; ++r)
#pragma unroll
            for (int j = 0; j < 4; ++j) {
                ulonglong2 t = *(const ulonglong2*)(q2S + (rl + r) * 8 + j * 2);
                q2[r][2*j] = t.x; q2[r][2*j+1] = t.y;
            }

        // ---- (a) denominator sweep for these 4 rows ----
        float ls[4] = {0.f, 0.f, 0.f, 0.f};
#pragma unroll 1
        for (int c = 0; c < 16; ++c) {
            const int col = c * 128 + lane * 4;
            u64 ka[8], kb[8];
#pragma unroll
            for (int d = 0; d < 8; ++d) {
                uint2 raw = *(const uint2*)(kSh + d * S + col);     // LDS.64
                float2 f01 = __half22float2(*(__half2*)&raw.x);
                float2 f23 = __half22float2(*(__half2*)&raw.y);
                ka[d] = pack2(f01.x, f01.y);
                kb[d] = pack2(f23.x, f23.y);
            }
#pragma unroll
            for (int r = 0; r < 4; ++r) {
                u64 sa = mul2u(q2[r][0], ka[0]);
                u64 sb = mul2u(q2[r][1], ka[1]);
                sa = fma2(q2[r][2], ka[2], sa); sb = fma2(q2[r][3], ka[3], sb);
                sa = fma2(q2[r][4], ka[4], sa); sb = fma2(q2[r][5], ka[5], sb);
                sa = fma2(q2[r][6], ka[6], sa); sb = fma2(q2[r][7], ka[7], sb);
                float2 s1 = unpk2(add2u(sa, sb));
                u64 ta = mul2u(q2[r][0], kb[0]);
                u64 tb = mul2u(q2[r][1], kb[1]);
                ta = fma2(q2[r][2], kb[2], ta); tb = fma2(q2[r][3], kb[3], tb);
                ta = fma2(q2[r][4], kb[4], ta); tb = fma2(q2[r][5], kb[5], tb);
                ta = fma2(q2[r][6], kb[6], ta); tb = fma2(q2[r][7], kb[7], tb);
                float2 s2 = unpk2(add2u(ta, tb));
                ls[r] += (ex2f(s1.x) + ex2f(s1.y)) + (ex2f(s2.x) + ex2f(s2.y));
            }
        }

        u64 iv2[4];
#pragma unroll
        for (int r = 0; r < 4; ++r) {
            float v = ls[r];
#pragma unroll
            for (int o = 16; o > 0; o >>= 1) v += __shfl_xor_sync(0xffffffffu, v, o);
            float iv = rcpf(v);
            iv2[r] = pack2(iv, iv);
        }

        // ---- (b) recompute + normalize + store sweep (same 4 rows) ----
        const size_t wb = ((size_t)hb * S + (size_t)tile * ROWS_CTA + rl) * S;
#pragma unroll 1
        for (int c = 0; c < 16; ++c) {
            const int col = c * 128 + lane * 4;
            u64 ka[8], kb[8];
#pragma unroll
            for (int d = 0; d < 8; ++d) {
                uint2 raw = *(const uint2*)(kSh + d * S + col);
                float2 f01 = __half22float2(*(__half2*)&raw.x);
                float2 f23 = __half22float2(*(__half2*)&raw.y);
                ka[d] = pack2(f01.x, f01.y);
                kb[d] = pack2(f23.x, f23.y);
            }
#pragma unroll
            for (int r = 0; r < 4; ++r) {
                u64 sa = mul2u(q2[r][0], ka[0]);
                u64 sb = mul2u(q2[r][1], ka[1]);
                sa = fma2(q2[r][2], ka[2], sa); sb = fma2(q2[r][3], ka[3], sb);
                sa = fma2(q2[r][4], ka[4], sa); sb = fma2(q2[r][5], ka[5], sb);
                sa = fma2(q2[r][6], ka[6], sa); sb = fma2(q2[r][7], ka[7], sb);
                float2 s1 = unpk2(add2u(sa, sb));
                u64 ta = mul2u(q2[r][0], kb[0]);
                u64 tb = mul2u(q2[r][1], kb[1]);
                ta = fma2(q2[r][2], kb[2], ta); tb = fma2(q2[r][3], kb[3], tb);
                ta = fma2(q2[r][4], kb[4], ta); tb = fma2(q2[r][5], kb[5], tb);
                ta = fma2(q2[r][6], kb[6], ta); tb = fma2(q2[r][7], kb[7], tb);
                float2 s2 = unpk2(add2u(ta, tb));

                u64 w0 = mul2u(pack2(ex2f(s1.x), ex2f(s1.y)), iv2[r]);
                u64 w1 = mul2u(pack2(ex2f(s2.x), ex2f(s2.y)), iv2[r]);
                float2 a = unpk2(w0);
                float2 b = unpk2(w1);
                csh[2*c+0] = __hadd2(csh[2*c+0], __floats2half2_rn(a.x, a.y));
                csh[2*c+1] = __hadd2(csh[2*c+1], __floats2half2_rn(b.x, b.y));
                __stcs((float4*)(wout + wb + (size_t)r * S + col),
                       make_float4(a.x, a.y, b.x, b.y));
            }
        }
    }

    // ---------------- fused head-sum: colsums -> smem, v -> dead k region ---
    __syncthreads();     // main loop done everywhere (k reads finished)
    {
        __half* csW = cshS + wrp * S;
#pragma unroll
        for (int c = 0; c < 16; ++c) {
            const int col = c * 128 + lane * 4;
            uint2 st;
            st.x = *(unsigned*)&csh[2*c+0];
            st.y = *(unsigned*)&csh[2*c+1];
            *(uint2*)(csW + col) = st;
        }
        // v fp16 tile into kSh (k no longer needed)
        const uint4* v4 = (const uint4*)(g_vTh + (size_t)hb * D * S);
        uint4* vd = (uint4*)kSh;
#pragma unroll
        for (int i = 0; i < 16; ++i) vd[tid + 128 * i] = v4[tid + 128 * i];
    }
    __syncthreads();
    {
        const int j0 = tid * 16;
        float csv[16];
#pragma unroll
        for (int jj = 0; jj < 16; ++jj) {
            float s = 0.f;
#pragma unroll
            for (int w = 0; w < 4; ++w)
                s += __half2float(cshS[w * S + j0 + jj]);
            csv[jj] = s;
        }
        float p[8];
#pragma unroll
        for (int d = 0; d < 8; ++d) {
            float s = 0.f;
#pragma unroll
            for (int jj = 0; jj < 16; ++jj)
                s += csv[jj] * __half2float(kSh[d * S + j0 + jj]);
            p[d] = s;
        }
        float* redS = (float*)q2S;
#pragma unroll
        for (int d = 0; d < 8; ++d) {
            float v = p[d];
#pragma unroll
            for (int o = 16; o > 0; o >>= 1) v += __shfl_xor_sync(0xffffffffu, v, o);
            p[d] = v;
        }
        if (lane == 0) {
#pragma unroll
            for (int d = 0; d < 8; ++d) redS[wrp * 8 + d] = p[d];
        }
        __syncthreads();
        if (tid < 8) {
            float s = redS[tid] + redS[8 + tid] + redS[16 + tid] + redS[24 + tid];
            g_hpart[((size_t)hb * 8 + tid) * TILES + tile] = s;   // transposed
        }
    }
}

// ---------------------------------------------------------------------------
// Kernel 3: out[b][f] = sum_{h,d} (sum_tile hpart[hb*8+d][tile]) * Wo[h*8+d][f]
// ---------------------------------------------------------------------------
__global__ void __launch_bounds__(256) out_kernel(
    const float* __restrict__ Wo, float* __restrict__ out)
{
    __shared__ float hs[256];
    const int t = threadIdx.x;
    {
        const int b = t >> 6, j = t & 63;
        const int h = j >> 3, d = j & 7;
        const int hb = h * 4 + b;
        const float* src = g_hpart + ((size_t)hb * 8 + d) * TILES;
        float s = 0.f;
#pragma unroll
        for (int i = 0; i < TILES / 4; ++i) {
            float4 a = *(const float4*)(src + 4 * i);
            s += (a.x + a.y) + (a.z + a.w);
        }
        hs[t] = s;
    }
    __syncthreads();
    const int b = t >> 6, f = t & 63;
    float a = 0.f;
#pragma unroll
    for (int j = 0; j < 64; ++j)
        a = fmaf(hs[b * 64 + j], Wo[j * 64 + f], a);
    out[b * 64 + f] = a;
}

// ---------------------------------------------------------------------------
extern "C" void kernel_launch(void* const* d_in, const int* in_sizes, int n_in,
                              void* d_out, int out_size)
{
    const float* x  = (const float*)d_in[0];
    const float* Wq = (const float*)d_in[1];
    const float* Wk = (const float*)d_in[2];
    const float* Wv = (const float*)d_in[3];
    const float* Wo = (const float*)d_in[4];
    float* out = (float*)d_out;

    const long long WELEMS = (long long)HB * S * S;  // 134217728
    float* wout = out;
    bool has_sum = false;
    if ((long long)out_size >= WELEMS + 256) {  // [sum(256) | weights]
        wout = out + 256;
        has_sum = true;
    }

    const int k2_smem = (8192 + 1024 + 4096) * 4;   // 53248
    cudaFuncSetAttribute(attn_kernel, cudaFuncAttributeMaxDynamicSharedMemorySize, k2_smem);

    qkv_kernel<<<(B * S) / K1_ROWS, 192>>>(x, Wq, Wk, Wv);
    attn_kernel<<<dim3(TILES, HB), 128, k2_smem>>>(wout);
    if (has_sum) out_kernel<<<1, 256>>>(Wo, out);
}